// round 1
// baseline (speedup 1.0000x reference)
#include <cuda_runtime.h>
#include <cstdint>
#include <math.h>

// Problem constants
#define D_MODEL 1024
#define NHEADS  16
#define DK      64
#define BATCH   2048
#define SEQ     20
#define M_TOTAL (BATCH * SEQ)   // 40960

// ---------------------------------------------------------------------------
// Scratch: q/k/v projections, fp32, [M_TOTAL, D_MODEL] each (natural layout)
// ---------------------------------------------------------------------------
__device__ float g_q[(size_t)M_TOTAL * D_MODEL];
__device__ float g_k[(size_t)M_TOTAL * D_MODEL];
__device__ float g_v[(size_t)M_TOTAL * D_MODEL];

// ---------------------------------------------------------------------------
// tf32 m16n8k8 MMA
// ---------------------------------------------------------------------------
__device__ __forceinline__ void mma_tf32(float* c, const uint32_t* a, const uint32_t* b) {
    asm volatile(
        "mma.sync.aligned.m16n8k8.row.col.f32.tf32.tf32.f32 "
        "{%0,%1,%2,%3}, {%4,%5,%6,%7}, {%8,%9}, {%0,%1,%2,%3};"
        : "+f"(c[0]), "+f"(c[1]), "+f"(c[2]), "+f"(c[3])
        : "r"(a[0]), "r"(a[1]), "r"(a[2]), "r"(a[3]),
          "r"(b[0]), "r"(b[1]));
}

__device__ __forceinline__ void cp_async16(void* smem_ptr, const void* gptr) {
    uint32_t s = (uint32_t)__cvta_generic_to_shared(smem_ptr);
    asm volatile("cp.async.cg.shared.global [%0], [%1], 16;\n" :: "r"(s), "l"(gptr));
}
#define CP_COMMIT() asm volatile("cp.async.commit_group;\n" ::: "memory")
#define CP_WAIT(n)  asm volatile("cp.async.wait_group %0;\n" :: "n"(n) : "memory")

// ---------------------------------------------------------------------------
// Projection GEMM: Y = X @ W^T + b  for W in {W_Q, W_K, W_V}
// X: [40960, 1024] fp32.  W: [1024, 1024] (row n contiguous in k).
// Tiles: BM=128, BN=128, BK=32.  256 threads = 8 warps (2x4), warp tile 64x32.
// smem row stride = 36 floats -> bank index (4*r + c) mod 32: conflict-free
// fragment loads for the m16n8k8 access pattern.
// ---------------------------------------------------------------------------
#define BM 128
#define BN 128
#define BK 32
#define SSTRIDE 36
#define TILE_FLOATS (128 * SSTRIDE)          // 4608 floats per tile
#define SMEM_BYTES  (4 * TILE_FLOATS * 4)    // 2 bufs x (A + B) = 73728 B

__global__ __launch_bounds__(256) void proj_gemm(
    const float* __restrict__ X,
    const float* __restrict__ Wq, const float* __restrict__ bq,
    const float* __restrict__ Wk, const float* __restrict__ bk,
    const float* __restrict__ Wv, const float* __restrict__ bv)
{
    extern __shared__ float smem[];
    float* sA0 = smem;
    float* sB0 = smem + TILE_FLOATS;
    float* sA1 = smem + 2 * TILE_FLOATS;
    float* sB1 = smem + 3 * TILE_FLOATS;

    const int tid  = threadIdx.x;
    const int lane = tid & 31;
    const int warp = tid >> 5;
    const int wr   = warp >> 2;       // 0..1  (warp row, 64 rows each)
    const int wc   = warp & 3;        // 0..3  (warp col, 32 cols each)
    const int g    = lane >> 2;       // 0..7
    const int tq   = lane & 3;        // 0..3

    const int mBase = blockIdx.x * BM;            // M block (0..319)
    const int w     = blockIdx.y >> 3;            // which projection 0/1/2
    const int nBase = (blockIdx.y & 7) * BN;      // 0..896

    const float* Wp  = (w == 0) ? Wq : (w == 1) ? Wk : Wv;
    const float* bp  = (w == 0) ? bq : (w == 1) ? bk : bv;
    float*       outp = (w == 0) ? g_q : (w == 1) ? g_k : g_v;

    // Async tile loader: 128x32 floats each for A (X rows) and B (W rows).
    auto load_tiles = [&](float* dA, float* dB, int k0) {
        #pragma unroll
        for (int i = 0; i < 4; i++) {
            int chunk = tid + i * 256;            // 0..1023
            int r  = chunk >> 3;
            int c4 = (chunk & 7) * 4;
            cp_async16(&dA[r * SSTRIDE + c4],
                       &X[(size_t)(mBase + r) * D_MODEL + k0 + c4]);
        }
        #pragma unroll
        for (int i = 0; i < 4; i++) {
            int chunk = tid + i * 256;
            int r  = chunk >> 3;
            int c4 = (chunk & 7) * 4;
            cp_async16(&dB[r * SSTRIDE + c4],
                       &Wp[(size_t)(nBase + r) * D_MODEL + k0 + c4]);
        }
        CP_COMMIT();
    };

    float c[4][4][4];
    #pragma unroll
    for (int mt = 0; mt < 4; mt++)
        #pragma unroll
        for (int nt = 0; nt < 4; nt++)
            #pragma unroll
            for (int i = 0; i < 4; i++) c[mt][nt][i] = 0.f;

    load_tiles(sA0, sB0, 0);

    const int KT = D_MODEL / BK;   // 32
    int buf = 0;
    for (int kt = 0; kt < KT; kt++) {
        if (kt + 1 < KT) {
            load_tiles(buf ? sA0 : sA1, buf ? sB0 : sB1, (kt + 1) * BK);
            CP_WAIT(1);
        } else {
            CP_WAIT(0);
        }
        __syncthreads();

        const float* sAb = buf ? sA1 : sA0;
        const float* sBb = buf ? sB1 : sB0;

        #pragma unroll
        for (int ks = 0; ks < 4; ks++) {
            const int kk = ks * 8;
            uint32_t af[4][4], bf[4][2];
            #pragma unroll
            for (int mt = 0; mt < 4; mt++) {
                const float* base = &sAb[(wr * 64 + mt * 16 + g) * SSTRIDE + kk + tq];
                af[mt][0] = __float_as_uint(base[0]);
                af[mt][1] = __float_as_uint(base[8 * SSTRIDE]);
                af[mt][2] = __float_as_uint(base[4]);
                af[mt][3] = __float_as_uint(base[8 * SSTRIDE + 4]);
            }
            #pragma unroll
            for (int nt = 0; nt < 4; nt++) {
                const float* base = &sBb[(wc * 32 + nt * 8 + g) * SSTRIDE + kk + tq];
                bf[nt][0] = __float_as_uint(base[0]);
                bf[nt][1] = __float_as_uint(base[4]);
            }
            #pragma unroll
            for (int mt = 0; mt < 4; mt++)
                #pragma unroll
                for (int nt = 0; nt < 4; nt++)
                    mma_tf32(c[mt][nt], af[mt], bf[nt]);
        }
        __syncthreads();
        buf ^= 1;
    }

    // Epilogue: add bias, store.
    #pragma unroll
    for (int mt = 0; mt < 4; mt++) {
        #pragma unroll
        for (int nt = 0; nt < 4; nt++) {
            int row = mBase + wr * 64 + mt * 16 + g;
            int col = nBase + wc * 32 + nt * 8 + 2 * tq;
            float b0 = bp[col], b1 = bp[col + 1];
            float2 v01 = make_float2(c[mt][nt][0] + b0, c[mt][nt][1] + b1);
            float2 v23 = make_float2(c[mt][nt][2] + b0, c[mt][nt][3] + b1);
            *(float2*)&outp[(size_t)row * D_MODEL + col] = v01;
            *(float2*)&outp[(size_t)(row + 8) * D_MODEL + col] = v23;
        }
    }
}

// ---------------------------------------------------------------------------
// Attention + decay epilogue. One block per (b, h). 128 threads.
// out[b,s,h*64+d] = sum_j ( attn[i,j] - |i-j| ) * v[j,d]
//   attn[i,j] = m_j * exp(q_i.k_j / 8) / (sum_j m_j exp(...) + 1e-8)
// ---------------------------------------------------------------------------
__global__ __launch_bounds__(128) void attn_kernel(
    const int* __restrict__ lenbuf, float* __restrict__ out)
{
    const int bh = blockIdx.x;
    const int b  = bh >> 4;
    const int h  = bh & 15;
    const int tid = threadIdx.x;

    __shared__ float sq[SEQ][65], sk[SEQ][65], sv[SEQ][65];
    __shared__ float ssc[SEQ][21];
    __shared__ float sinv[SEQ];

    // Load q/k/v tiles [20,64]
    for (int e = tid; e < SEQ * DK; e += 128) {
        int s = e >> 6, d = e & 63;
        size_t gi = (size_t)(b * SEQ + s) * D_MODEL + h * DK + d;
        sq[s][d] = g_q[gi];
        sk[s][d] = g_k[gi];
        sv[s][d] = g_v[gi];
    }
    __syncthreads();

    // length may be stored as int64 or int32 depending on jax x64 config.
    // All lengths >= 1, so int32-view index 1 is 0 iff the buffer is int64.
    bool is64 = (lenbuf[1] == 0);
    int len = is64 ? lenbuf[2 * b] : lenbuf[b];

    // Scores: exp(q.k/8) with key-side mask j < len
    for (int p = tid; p < SEQ * SEQ; p += 128) {
        int i = p / SEQ, j = p % SEQ;
        float acc = 0.f;
        #pragma unroll
        for (int d = 0; d < DK; d++) acc += sq[i][d] * sk[j][d];
        ssc[i][j] = (j < len) ? expf(acc * 0.125f) : 0.f;
    }
    __syncthreads();

    if (tid < SEQ) {
        float s = 0.f;
        #pragma unroll
        for (int j = 0; j < SEQ; j++) s += ssc[tid][j];
        sinv[tid] = 1.f / (s + 1e-8f);
    }
    __syncthreads();

    // Output: (attn - |i-j|) weighted sum over v
    for (int e = tid; e < SEQ * DK; e += 128) {
        int i = e >> 6, d = e & 63;
        float inv = sinv[i];
        float acc = 0.f;
        #pragma unroll
        for (int j = 0; j < SEQ; j++) {
            float wgt = ssc[i][j] * inv - (float)((i > j) ? (i - j) : (j - i));
            acc += wgt * sv[j][d];
        }
        out[(size_t)(b * SEQ + i) * D_MODEL + h * DK + d] = acc;
    }
}

// ---------------------------------------------------------------------------
// Inputs (metadata order): Q, W_Q, b_Q, W_K, b_K, W_V, b_V, length
// ---------------------------------------------------------------------------
extern "C" void kernel_launch(void* const* d_in, const int* in_sizes, int n_in,
                              void* d_out, int out_size)
{
    const float* X  = (const float*)d_in[0];
    const float* Wq = (const float*)d_in[1];
    const float* bq = (const float*)d_in[2];
    const float* Wk = (const float*)d_in[3];
    const float* bk = (const float*)d_in[4];
    const float* Wv = (const float*)d_in[5];
    const float* bv = (const float*)d_in[6];
    const int*   ln = (const int*)d_in[7];

    cudaFuncSetAttribute(proj_gemm,
                         cudaFuncAttributeMaxDynamicSharedMemorySize, SMEM_BYTES);

    dim3 grid(M_TOTAL / BM, 3 * (D_MODEL / BN));   // 320 x 24
    proj_gemm<<<grid, 256, SMEM_BYTES>>>(X, Wq, bq, Wk, bk, Wv, bv);

    attn_kernel<<<BATCH * NHEADS, 128>>>(ln, (float*)d_out);
}

// round 3
// speedup vs baseline: 1.5253x; 1.5253x over previous
#include <cuda_runtime.h>
#include <cuda_fp16.h>
#include <cstdint>
#include <math.h>

// Problem constants
#define D_MODEL 1024
#define NHEADS  16
#define DK      64
#define BATCH   2048
#define SEQ     20
#define M_TOTAL (BATCH * SEQ)   // 40960

// ---------------------------------------------------------------------------
// Scratch
// ---------------------------------------------------------------------------
__device__ float  g_q[(size_t)M_TOTAL * D_MODEL];
__device__ float  g_k[(size_t)M_TOTAL * D_MODEL];
__device__ float  g_v[(size_t)M_TOTAL * D_MODEL];
__device__ __half g_xh[(size_t)M_TOTAL * D_MODEL];
__device__ __half g_wh[3][(size_t)D_MODEL * D_MODEL];

// ---------------------------------------------------------------------------
// fp32 -> fp16 conversion (vectorized)
// ---------------------------------------------------------------------------
struct alignas(8) Half4 { __half2 a, b; };

__global__ __launch_bounds__(256) void f2h_kernel(
    const float* __restrict__ src, __half* __restrict__ dst, int n4)
{
    int i = blockIdx.x * blockDim.x + threadIdx.x;
    if (i < n4) {
        float4 v = ((const float4*)src)[i];
        Half4 h;
        h.a = __floats2half2_rn(v.x, v.y);
        h.b = __floats2half2_rn(v.z, v.w);
        ((Half4*)dst)[i] = h;
    }
}

// ---------------------------------------------------------------------------
// fp16 m16n8k16 MMA, fp32 accumulate
// ---------------------------------------------------------------------------
__device__ __forceinline__ void mma16(float* c, const uint32_t* a, const uint32_t* b) {
    asm volatile(
        "mma.sync.aligned.m16n8k16.row.col.f32.f16.f16.f32 "
        "{%0,%1,%2,%3}, {%4,%5,%6,%7}, {%8,%9}, {%0,%1,%2,%3};"
        : "+f"(c[0]), "+f"(c[1]), "+f"(c[2]), "+f"(c[3])
        : "r"(a[0]), "r"(a[1]), "r"(a[2]), "r"(a[3]),
          "r"(b[0]), "r"(b[1]));
}

__device__ __forceinline__ void cp16(uint32_t saddr, const void* g) {
    asm volatile("cp.async.cg.shared.global [%0], [%1], 16;\n" :: "r"(saddr), "l"(g));
}
#define CP_COMMIT() asm volatile("cp.async.commit_group;\n" ::: "memory")
#define CP_WAIT(n)  asm volatile("cp.async.wait_group %0;\n" :: "n"(n) : "memory")

__device__ __forceinline__ uint32_t smem_u32(const void* p) {
    uint32_t a;
    asm("{ .reg .u64 t; cvta.to.shared.u64 t, %1; cvt.u32.u64 %0, t; }"
        : "=r"(a) : "l"(p));
    return a;
}

// ---------------------------------------------------------------------------
// Projection GEMM (fp16 tensor cores): Y = X @ W^T + b for Q/K/V.
// BM=128, BN=256, BK=32. 256 threads = 8 warps (2x4), warp tile 64x64.
// Smem rows stored with 20-word (40-half) stride: fragment LDS pattern
// (g*20 + tq + {0,4}) mod 32 covers all banks -> conflict-free.
// 3-stage cp.async pipeline.
// ---------------------------------------------------------------------------
#define GM_BM 128
#define GM_BN 256
#define GM_BK 32
#define WSTRIDE 20                        // 32-bit words per smem row
#define A_STG_WORDS (GM_BM * WSTRIDE)     // 2560
#define B_STG_WORDS (GM_BN * WSTRIDE)     // 5120
#define STG_WORDS   (A_STG_WORDS + B_STG_WORDS)  // 7680 (30720 B)
#define NSTAGE 3
#define GM_SMEM_BYTES (NSTAGE * STG_WORDS * 4)   // 92160
#define GM_KT (D_MODEL / GM_BK)           // 32

__global__ __launch_bounds__(256, 1) void proj_gemm(
    const float* __restrict__ bq, const float* __restrict__ bk, const float* __restrict__ bv)
{
    extern __shared__ uint32_t smem[];
    const uint32_t sb = smem_u32(smem);

    const int tid  = threadIdx.x;
    const int lane = tid & 31;
    const int warp = tid >> 5;
    const int wr   = warp >> 2;     // 0..1
    const int wc   = warp & 3;      // 0..3
    const int g    = lane >> 2;     // 0..7
    const int tq   = lane & 3;      // 0..3

    const int proj  = blockIdx.x >> 2;
    const int nBase = (blockIdx.x & 3) * GM_BN;
    const int mBase = blockIdx.y * GM_BM;

    const __half* Wp = g_wh[proj];

    // stage loader: A 128x32 halves, B 256x32 halves, 16B chunks
    auto load_stage = [&](int stg, int kt) {
        uint32_t base = sb + stg * (STG_WORDS * 4);
        int k0 = kt * GM_BK;
        #pragma unroll
        for (int i = 0; i < 2; i++) {
            int ch = tid + i * 256;            // 0..511
            int r = ch >> 2, c = ch & 3;
            cp16(base + (r * WSTRIDE + c * 4) * 4,
                 &g_xh[(size_t)(mBase + r) * D_MODEL + k0 + c * 8]);
        }
        #pragma unroll
        for (int i = 0; i < 4; i++) {
            int ch = tid + i * 256;            // 0..1023
            int r = ch >> 2, c = ch & 3;
            cp16(base + (A_STG_WORDS + r * WSTRIDE + c * 4) * 4,
                 &Wp[(size_t)(nBase + r) * D_MODEL + k0 + c * 8]);
        }
        CP_COMMIT();
    };

    float c[4][8][4];
    #pragma unroll
    for (int mt = 0; mt < 4; mt++)
        #pragma unroll
        for (int nt = 0; nt < 8; nt++)
            #pragma unroll
            for (int i = 0; i < 4; i++) c[mt][nt][i] = 0.f;

    load_stage(0, 0);
    load_stage(1, 1);

    for (int kt = 0; kt < GM_KT; kt++) {
        int stg = kt % NSTAGE;
        if (kt + 2 < GM_KT) load_stage((kt + 2) % NSTAGE, kt + 2);
        if (kt < GM_KT - 2)      CP_WAIT(2);
        else if (kt == GM_KT - 2) CP_WAIT(1);
        else                      CP_WAIT(0);
        __syncthreads();

        const uint32_t* sAw = smem + stg * STG_WORDS;
        const uint32_t* sBw = sAw + A_STG_WORDS;

        #pragma unroll
        for (int ks = 0; ks < 2; ks++) {
            const int kw = ks * 8 + tq;
            uint32_t af[4][4], bf[8][2];
            #pragma unroll
            for (int mt = 0; mt < 4; mt++) {
                int rb = (wr * 64 + mt * 16 + g) * WSTRIDE + kw;
                af[mt][0] = sAw[rb];
                af[mt][1] = sAw[rb + 8 * WSTRIDE];
                af[mt][2] = sAw[rb + 4];
                af[mt][3] = sAw[rb + 8 * WSTRIDE + 4];
            }
            #pragma unroll
            for (int nt = 0; nt < 8; nt++) {
                int rb = (wc * 64 + nt * 8 + g) * WSTRIDE + kw;
                bf[nt][0] = sBw[rb];
                bf[nt][1] = sBw[rb + 4];
            }
            #pragma unroll
            for (int mt = 0; mt < 4; mt++)
                #pragma unroll
                for (int nt = 0; nt < 8; nt++)
                    mma16(c[mt][nt], af[mt], bf[nt]);
        }
        __syncthreads();
    }

    // Epilogue: bias add + store fp32
    const float* bp   = (proj == 0) ? bq : (proj == 1) ? bk : bv;
    float*       outp = (proj == 0) ? g_q : (proj == 1) ? g_k : g_v;
    #pragma unroll
    for (int mt = 0; mt < 4; mt++) {
        #pragma unroll
        for (int nt = 0; nt < 8; nt++) {
            int row = mBase + wr * 64 + mt * 16 + g;
            int col = nBase + wc * 64 + nt * 8 + 2 * tq;
            float b0 = bp[col], b1 = bp[col + 1];
            float2 v01 = make_float2(c[mt][nt][0] + b0, c[mt][nt][1] + b1);
            float2 v23 = make_float2(c[mt][nt][2] + b0, c[mt][nt][3] + b1);
            *(float2*)&outp[(size_t)row * D_MODEL + col] = v01;
            *(float2*)&outp[(size_t)(row + 8) * D_MODEL + col] = v23;
        }
    }
}

// ---------------------------------------------------------------------------
// Attention + decay epilogue, register-blocked. Block per (b,h), 128 threads.
// ---------------------------------------------------------------------------
__global__ __launch_bounds__(128) void attn_kernel(
    const int* __restrict__ lenbuf, float* __restrict__ out)
{
    const int bh = blockIdx.x;
    const int b  = bh >> 4;
    const int h  = bh & 15;
    const int tid = threadIdx.x;

    __shared__ __align__(16) float sq[SEQ][68];
    __shared__ __align__(16) float sk[SEQ][68];
    __shared__ __align__(16) float sv[SEQ][68];
    __shared__ float ssc[SEQ][24];
    __shared__ float sinv[SEQ];

    {
        size_t base = (size_t)(b * SEQ) * D_MODEL + h * DK;
        for (int e = tid; e < SEQ * (DK / 4); e += 128) {
            int s = e >> 4, d4 = (e & 15) * 4;
            size_t gi = base + (size_t)s * D_MODEL + d4;
            *(float4*)&sq[s][d4] = *(const float4*)&g_q[gi];
            *(float4*)&sk[s][d4] = *(const float4*)&g_k[gi];
            *(float4*)&sv[s][d4] = *(const float4*)&g_v[gi];
        }
    }
    __syncthreads();

    // length may be int64 or int32 (jax x64 config). All lengths >= 1,
    // so int32-view word 1 == 0 iff buffer is int64.
    bool is64 = (lenbuf[1] == 0);
    int len = is64 ? lenbuf[2 * b] : lenbuf[b];

    // Scores: 2x2 register tiles on threads 0..99
    if (tid < 100) {
        int i0 = (tid / 10) * 2, j0 = (tid % 10) * 2;
        float a00 = 0.f, a01 = 0.f, a10 = 0.f, a11 = 0.f;
        #pragma unroll 8
        for (int d = 0; d < DK; d++) {
            float q0 = sq[i0][d], q1 = sq[i0 + 1][d];
            float k0 = sk[j0][d], k1 = sk[j0 + 1][d];
            a00 += q0 * k0; a01 += q0 * k1;
            a10 += q1 * k0; a11 += q1 * k1;
        }
        bool m0 = (j0 < len), m1 = (j0 + 1 < len);
        ssc[i0][j0]         = m0 ? __expf(a00 * 0.125f) : 0.f;
        ssc[i0][j0 + 1]     = m1 ? __expf(a01 * 0.125f) : 0.f;
        ssc[i0 + 1][j0]     = m0 ? __expf(a10 * 0.125f) : 0.f;
        ssc[i0 + 1][j0 + 1] = m1 ? __expf(a11 * 0.125f) : 0.f;
    }
    __syncthreads();

    if (tid < SEQ) {
        float s = 0.f;
        #pragma unroll
        for (int j = 0; j < SEQ; j++) s += ssc[tid][j];
        sinv[tid] = 1.f / (s + 1e-8f);
    }
    __syncthreads();

    // Output: 4 rows x 4 cols per thread on threads 0..79
    if (tid < 80) {
        int i0 = (tid / 16) * 4;
        int d0 = (tid & 15) * 4;
        float s0 = sinv[i0], s1 = sinv[i0 + 1], s2 = sinv[i0 + 2], s3 = sinv[i0 + 3];
        float fi0 = (float)i0;
        float4 o0 = {0, 0, 0, 0}, o1 = {0, 0, 0, 0}, o2 = {0, 0, 0, 0}, o3 = {0, 0, 0, 0};
        float fj = 0.f;
        #pragma unroll
        for (int j = 0; j < SEQ; j++) {
            float4 vv = *(const float4*)&sv[j][d0];
            float w0 = ssc[i0][j]     * s0 - fabsf(fi0 - fj);
            float w1 = ssc[i0 + 1][j] * s1 - fabsf(fi0 + 1.f - fj);
            float w2 = ssc[i0 + 2][j] * s2 - fabsf(fi0 + 2.f - fj);
            float w3 = ssc[i0 + 3][j] * s3 - fabsf(fi0 + 3.f - fj);
            o0.x += w0 * vv.x; o0.y += w0 * vv.y; o0.z += w0 * vv.z; o0.w += w0 * vv.w;
            o1.x += w1 * vv.x; o1.y += w1 * vv.y; o1.z += w1 * vv.z; o1.w += w1 * vv.w;
            o2.x += w2 * vv.x; o2.y += w2 * vv.y; o2.z += w2 * vv.z; o2.w += w2 * vv.w;
            o3.x += w3 * vv.x; o3.y += w3 * vv.y; o3.z += w3 * vv.z; o3.w += w3 * vv.w;
            fj += 1.f;
        }
        size_t base = (size_t)(b * SEQ + i0) * D_MODEL + h * DK + d0;
        *(float4*)&out[base]               = o0;
        *(float4*)&out[base + D_MODEL]     = o1;
        *(float4*)&out[base + 2 * D_MODEL] = o2;
        *(float4*)&out[base + 3 * D_MODEL] = o3;
    }
}

// ---------------------------------------------------------------------------
// Inputs (metadata order): Q, W_Q, b_Q, W_K, b_K, W_V, b_V, length
// ---------------------------------------------------------------------------
extern "C" void kernel_launch(void* const* d_in, const int* in_sizes, int n_in,
                              void* d_out, int out_size)
{
    const float* X  = (const float*)d_in[0];
    const float* Wq = (const float*)d_in[1];
    const float* bq = (const float*)d_in[2];
    const float* Wk = (const float*)d_in[3];
    const float* bk = (const float*)d_in[4];
    const float* Wv = (const float*)d_in[5];
    const float* bv = (const float*)d_in[6];
    const int*   ln = (const int*)d_in[7];

    // Resolve device addresses of __device__ scratch for the conversion pass
    __half* xh; cudaGetSymbolAddress((void**)&xh, g_xh);
    __half* wh; cudaGetSymbolAddress((void**)&wh, g_wh);

    // fp32 -> fp16 conversions
    {
        int n4 = M_TOTAL * D_MODEL / 4;                 // 10485760
        f2h_kernel<<<(n4 + 255) / 256, 256>>>(X, xh, n4);
        int w4 = D_MODEL * D_MODEL / 4;                 // 262144
        f2h_kernel<<<(w4 + 255) / 256, 256>>>(Wq, wh + 0 * (size_t)D_MODEL * D_MODEL, w4);
        f2h_kernel<<<(w4 + 255) / 256, 256>>>(Wk, wh + 1 * (size_t)D_MODEL * D_MODEL, w4);
        f2h_kernel<<<(w4 + 255) / 256, 256>>>(Wv, wh + 2 * (size_t)D_MODEL * D_MODEL, w4);
    }

    cudaFuncSetAttribute(proj_gemm,
                         cudaFuncAttributeMaxDynamicSharedMemorySize, GM_SMEM_BYTES);

    // grid.x fastest = (proj, n-tile): X m-tile reused 12x from L2, W resident
    dim3 grid(3 * (D_MODEL / GM_BN), M_TOTAL / GM_BM);   // (12, 320)
    proj_gemm<<<grid, 256, GM_SMEM_BYTES>>>(bq, bk, bv);

    attn_kernel<<<BATCH * NHEADS, 128>>>(ln, (float*)d_out);
}